// round 1
// baseline (speedup 1.0000x reference)
#include <cuda_runtime.h>
#include <cuda_bf16.h>

// Problem constants (match reference)
#define N_MOL   8
#define MA      24
#define DESIGN  26
#define RADIAL  15
#define MS      (RADIAL * DESIGN)        // 390 samples per atom
#define MXP     (MA * MS)                // 9360 grid points per molecule
#define RM_C    5.0f
#define PI_F    3.14159265358979323846f

// Output layout: concat(grid [N,MXP,3], dv [N,MXP,MA,3], weights [N,MXP])
#define GRID_FLOATS (N_MOL * MXP * 3)              // 224640
#define DV_OFF      GRID_FLOATS
#define DV_FLOATS   (N_MOL * MXP * MA * 3)         // 5391360
#define W_OFF       (DV_OFF + DV_FLOATS)           // 5616000
#define DV_THREADS  (N_MOL * MXP * MA)             // 1797120

__global__ __launch_bounds__(256)
void becke_kernel(const float* __restrict__ coords,   // [N, MA, 3]
                  const float* __restrict__ sphere,   // [DESIGN, 3]
                  const float* __restrict__ sw,       // [DESIGN]
                  float* __restrict__ out)
{
    __shared__ float cs[MA][3];
    __shared__ float dm[MA][MA];
    __shared__ float sph[DESIGN][3];
    __shared__ float sws[DESIGN];

    const int nmol = blockIdx.y;
    const int tid  = threadIdx.x;

    if (tid < MA * 3) cs[tid / 3][tid % 3] = coords[nmol * MA * 3 + tid];
    if (tid >= 128 && tid < 128 + DESIGN * 3) {
        int t = tid - 128;
        sph[t / 3][t % 3] = sphere[t];
    }
    if (tid >= 224 && tid < 224 + DESIGN) sws[tid - 224] = sw[tid - 224];
    __syncthreads();

    // interatomic distance matrix
    for (int e = tid; e < MA * MA; e += 256) {
        int i = e / MA, j = e % MA;
        float dx = cs[i][0] - cs[j][0];
        float dy = cs[i][1] - cs[j][1];
        float dz = cs[i][2] - cs[j][2];
        dm[i][j] = sqrtf(dx * dx + dy * dy + dz * dz);
    }
    __syncthreads();

    const int p = blockIdx.x * 256 + tid;    // grid point within molecule
    if (p >= MXP) return;

    const int am = p / MS;       // owning atom (center)
    const int k  = p % MS;       // sample index on the concentric grid
    const int a  = k / DESIGN;   // radial shell
    const int d  = k % DESIGN;   // angular point

    // Gauss-Chebyshev radial quadrature + Becke transform (f32, matches jnp)
    float fi  = (float)(a + 1);
    float z   = -cosf(PI_F * (2.0f * fi - 1.0f) / (2.0f * (float)RADIAL));
    float omz = 1.0f - z;
    float r   = RM_C * (1.0f + z) / omz;
    float dr  = 2.0f * RM_C / (omz * omz);
    float w   = sqrtf(1.0f - z * z) * dr * (PI_F / (float)RADIAL);
    w = r * r * 4.0f * PI_F * w;
    const float wt = sws[d] * w;

    const float gx = cs[am][0] + r * sph[d][0];
    const float gy = cs[am][1] + r * sph[d][1];
    const float gz = cs[am][2] + r * sph[d][2];

    // distances from grid point to every atom
    float rx[MA];
#pragma unroll
    for (int j = 0; j < MA; j++) {
        float dx = gx - cs[j][0];
        float dy = gy - cs[j][1];
        float dz = gz - cs[j][2];
        rx[j] = sqrtf(dx * dx + dy * dy + dz * dz);
    }

    // Becke cell functions. mu_ji = -mu_ij exactly in f32 (dm symmetric,
    // negation exact, softening polynomial is odd), so compute each unordered
    // pair once. Diagonal factor is exactly 1.0 after the +0.5*eye -> skipped.
    float cell[MA];
#pragma unroll
    for (int j = 0; j < MA; j++) cell[j] = 1.0f;

#pragma unroll
    for (int i = 0; i < MA; i++) {
#pragma unroll
        for (int j = i + 1; j < MA; j++) {
            float mu = (rx[i] - rx[j]) / fmaxf(dm[i][j], 1e-12f);
            mu = 0.5f * mu * (3.0f - mu * mu);   // softening pass 1
            mu = 0.5f * mu * (3.0f - mu * mu);   // softening pass 2
            cell[i] *= 0.5f * (1.0f - mu);
            cell[j] *= 0.5f * (1.0f + mu);
        }
    }

    float s   = 0.0f;
    float cam = 0.0f;
#pragma unroll
    for (int j = 0; j < MA; j++) {
        s += cell[j];
        if (j == am) cam = cell[j];   // predicated select, keeps cell[] in regs
    }
    const float v = cam / s;

    const int gp = nmol * MXP + p;
    out[3 * gp + 0] = gx;
    out[3 * gp + 1] = gy;
    out[3 * gp + 2] = gz;
    out[W_OFF + gp] = v * wt;
}

// dv[n,p,m,:] = grid[n,p,:] - coords[n,m,:]
// One thread per (n,p,m): 3 contiguous f32 stores -> fully coalesced stream.
__global__ __launch_bounds__(256)
void dv_kernel(const float* __restrict__ coords, float* __restrict__ out)
{
    const int t = blockIdx.x * 256 + threadIdx.x;
    if (t >= DV_THREADS) return;

    const int m  = t % MA;
    const int np = t / MA;           // n*MXP + p
    const int n  = np / MXP;

    const float* g = out + 3 * np;               // grid written by becke_kernel
    const float* c = coords + (n * MA + m) * 3;
    float* dvp = out + DV_OFF + 3 * t;

    dvp[0] = g[0] - c[0];
    dvp[1] = g[1] - c[1];
    dvp[2] = g[2] - c[2];
}

extern "C" void kernel_launch(void* const* d_in, const int* in_sizes, int n_in,
                              void* d_out, int out_size)
{
    // d_in[0]: labels (int32, unused -- padding is full for every molecule)
    const float* coords = (const float*)d_in[1];
    const float* sphere = (const float*)d_in[2];
    const float* sw     = (const float*)d_in[3];
    float* out = (float*)d_out;

    dim3 g1((MXP + 255) / 256, N_MOL);
    becke_kernel<<<g1, 256>>>(coords, sphere, sw, out);

    dv_kernel<<<(DV_THREADS + 255) / 256, 256>>>(coords, out);
}

// round 2
// speedup vs baseline: 1.4760x; 1.4760x over previous
#include <cuda_runtime.h>
#include <cuda_bf16.h>

// Problem constants (match reference)
#define N_MOL   8
#define MA      24
#define DESIGN  26
#define RADIAL  15
#define MS      (RADIAL * DESIGN)        // 390 samples per atom
#define MSH     (MS / 2)                 // 195: two points per thread
#define MXP     (MA * MS)                // 9360 grid points per molecule
#define RM_C    5.0f
#define PI_F    3.14159265358979323846f

// Output layout: concat(grid [N,MXP,3], dv [N,MXP,MA,3], weights [N,MXP])
#define GRID_FLOATS (N_MOL * MXP * 3)              // 224640
#define DV_OFF      GRID_FLOATS
#define DV_FLOATS   (N_MOL * MXP * MA * 3)         // 5391360
#define W_OFF       (DV_OFF + DV_FLOATS)           // 5616000

typedef unsigned long long u64;

// ---- packed f32x2 helpers (Blackwell sm_100+; ptxas never auto-fuses) ----
__device__ __forceinline__ u64 pk(float lo, float hi) {
    u64 r; asm("mov.b64 %0, {%1, %2};" : "=l"(r) : "f"(lo), "f"(hi)); return r;
}
__device__ __forceinline__ void upk(u64 v, float& lo, float& hi) {
    asm("mov.b64 {%0, %1}, %2;" : "=f"(lo), "=f"(hi) : "l"(v));
}
__device__ __forceinline__ u64 fma2(u64 a, u64 b, u64 c) {
    u64 r; asm("fma.rn.f32x2 %0, %1, %2, %3;" : "=l"(r) : "l"(a), "l"(b), "l"(c)); return r;
}
__device__ __forceinline__ u64 mul2(u64 a, u64 b) {
    u64 r; asm("mul.rn.f32x2 %0, %1, %2;" : "=l"(r) : "l"(a), "l"(b)); return r;
}
__device__ __forceinline__ u64 add2(u64 a, u64 b) {
    u64 r; asm("add.rn.f32x2 %0, %1, %2;" : "=l"(r) : "l"(a), "l"(b)); return r;
}

// ============================================================================
// Becke kernel: one thread handles TWO grid points (k and k+195) of the same
// owning atom, all pair math in packed f32x2. Reciprocal dm precomputed.
// ============================================================================
__global__ __launch_bounds__(256)
void becke_kernel(const float* __restrict__ coords,   // [N, MA, 3]
                  const float* __restrict__ sphere,   // [DESIGN, 3]
                  const float* __restrict__ sw,       // [DESIGN]
                  float* __restrict__ out)
{
    __shared__ float cs[MA][3];
    __shared__ u64   scs2[MA][3];       // duplicated-packed coords
    __shared__ u64   srdm2[MA][MA];     // duplicated-packed 1/max(dm,1e-12)
    __shared__ float sph[DESIGN][3];
    __shared__ float sws[DESIGN];

    const int nmol = blockIdx.y;
    const int tid  = threadIdx.x;

    if (tid < MA * 3) cs[tid / 3][tid % 3] = coords[nmol * MA * 3 + tid];
    if (tid >= 128 && tid < 128 + DESIGN * 3) {
        int t = tid - 128;
        sph[t / 3][t % 3] = sphere[t];
    }
    if (tid >= 224 && tid < 224 + DESIGN) sws[tid - 224] = sw[tid - 224];
    __syncthreads();

    for (int e = tid; e < MA * MA; e += 256) {
        int i = e / MA, j = e % MA;
        float dx = cs[i][0] - cs[j][0];
        float dy = cs[i][1] - cs[j][1];
        float dz = cs[i][2] - cs[j][2];
        float d  = sqrtf(dx * dx + dy * dy + dz * dz);
        float rc = 1.0f / fmaxf(d, 1e-12f);
        srdm2[i][j] = pk(rc, rc);
    }
    if (tid < MA * 3) {
        float v = cs[tid / 3][tid % 3];
        scs2[tid / 3][tid % 3] = pk(v, v);
    }
    __syncthreads();

    const int q = blockIdx.x * 256 + tid;        // [0, MA*MSH) per molecule
    if (q >= MA * MSH) return;

    const int am = q / MSH;
    const int k0 = q % MSH;
    const int k1 = k0 + MSH;

    const float cax = cs[am][0], cay = cs[am][1], caz = cs[am][2];

    // radial shell + weights + grid coords, scalar per half
    float gx0, gy0, gz0, wt0, gx1, gy1, gz1, wt1;
    {
        int a = k0 / DESIGN, d = k0 % DESIGN;
        float fi = (float)(a + 1);
        float z  = -cosf(PI_F * (2.0f * fi - 1.0f) / (2.0f * (float)RADIAL));
        float omz = 1.0f - z;
        float r   = RM_C * (1.0f + z) / omz;
        float dr  = 2.0f * RM_C / (omz * omz);
        float w   = sqrtf(1.0f - z * z) * dr * (PI_F / (float)RADIAL);
        wt0 = sws[d] * (r * r * 4.0f * PI_F * w);
        gx0 = cax + r * sph[d][0];
        gy0 = cay + r * sph[d][1];
        gz0 = caz + r * sph[d][2];
    }
    {
        int a = k1 / DESIGN, d = k1 % DESIGN;
        float fi = (float)(a + 1);
        float z  = -cosf(PI_F * (2.0f * fi - 1.0f) / (2.0f * (float)RADIAL));
        float omz = 1.0f - z;
        float r   = RM_C * (1.0f + z) / omz;
        float dr  = 2.0f * RM_C / (omz * omz);
        float w   = sqrtf(1.0f - z * z) * dr * (PI_F / (float)RADIAL);
        wt1 = sws[d] * (r * r * 4.0f * PI_F * w);
        gx1 = cax + r * sph[d][0];
        gy1 = cay + r * sph[d][1];
        gz1 = caz + r * sph[d][2];
    }

    const u64 NEG1  = pk(-1.0f, -1.0f);
    const u64 THREE = pk(3.0f, 3.0f);
    const u64 HALF  = pk(0.5f, 0.5f);
    const u64 NHALF = pk(-0.5f, -0.5f);

    const u64 gx2 = pk(gx0, gx1), gy2 = pk(gy0, gy1), gz2 = pk(gz0, gz1);

    // distances to every atom, packed
    u64 rx2[MA];
#pragma unroll
    for (int j = 0; j < MA; j++) {
        u64 dx = fma2(scs2[j][0], NEG1, gx2);
        u64 dy = fma2(scs2[j][1], NEG1, gy2);
        u64 dz = fma2(scs2[j][2], NEG1, gz2);
        u64 s  = mul2(dx, dx);
        s = fma2(dy, dy, s);
        s = fma2(dz, dz, s);
        float s0, s1; upk(s, s0, s1);
        rx2[j] = pk(sqrtf(s0), sqrtf(s1));
    }

    // Becke cell functions, each unordered pair once (mu_ji = -mu_ij)
    u64 cell2[MA];
#pragma unroll
    for (int j = 0; j < MA; j++) cell2[j] = pk(1.0f, 1.0f);

#pragma unroll
    for (int i = 0; i < MA; i++) {
#pragma unroll
        for (int j = i + 1; j < MA; j++) {
            u64 dif = fma2(rx2[j], NEG1, rx2[i]);
            u64 mu  = mul2(dif, srdm2[i][j]);
            // softening pass 1: mu = 0.5*mu*(3-mu^2)
            u64 m2 = mul2(mu, mu);
            u64 t  = fma2(m2, NEG1, THREE);
            mu = mul2(mul2(mu, t), HALF);
            // softening pass 2
            m2 = mul2(mu, mu);
            t  = fma2(m2, NEG1, THREE);
            mu = mul2(mul2(mu, t), HALF);
            // cell[i] *= 0.5*(1-mu); cell[j] *= 0.5*(1+mu)
            u64 a = fma2(mu, NHALF, HALF);
            cell2[i] = mul2(cell2[i], a);
            u64 b = fma2(mu, HALF, HALF);
            cell2[j] = mul2(cell2[j], b);
        }
    }

    u64 ssum = cell2[0];
#pragma unroll
    for (int j = 1; j < MA; j++) ssum = add2(ssum, cell2[j]);

    u64 cam2 = cell2[0];
#pragma unroll
    for (int j = 1; j < MA; j++) if (j == am) cam2 = cell2[j];

    float s0, s1, c0, c1;
    upk(ssum, s0, s1);
    upk(cam2, c0, c1);
    const float v0 = c0 / s0;
    const float v1 = c1 / s1;

    const int gp0 = nmol * MXP + am * MS + k0;
    const int gp1 = gp0 + MSH;
    out[3 * gp0 + 0] = gx0;
    out[3 * gp0 + 1] = gy0;
    out[3 * gp0 + 2] = gz0;
    out[3 * gp1 + 0] = gx1;
    out[3 * gp1 + 1] = gy1;
    out[3 * gp1 + 2] = gz1;
    out[W_OFF + gp0] = v0 * wt0;
    out[W_OFF + gp1] = v1 * wt1;
}

// ============================================================================
// dv kernel: one thread per grid point (k-row of 72 floats).
// dv[gp][m][c] = g[c] - coords[m][c], computed as packed fma2 and stored
// as 18 STG.128 per row. Coords staged in shared, read as u64 pairs.
// ============================================================================
__global__ __launch_bounds__(256)
void dv_kernel(const float* __restrict__ coords, float* __restrict__ out)
{
    __shared__ __align__(16) float cst[MA * 3];

    const int nmol = blockIdx.z;
    const int am   = blockIdx.y;
    const int half = blockIdx.x;
    const int tid  = threadIdx.x;

    if (tid < MA * 3) cst[tid] = coords[nmol * MA * 3 + tid];
    __syncthreads();

    if (tid >= MSH) return;

    const int kk = half * MSH + tid;
    const int gp = nmol * MXP + am * MS + kk;

    const float g0 = out[3 * gp + 0];
    const float g1 = out[3 * gp + 1];
    const float g2 = out[3 * gp + 2];

    const u64 NEG1 = pk(-1.0f, -1.0f);
    u64 P[3];
    P[0] = pk(g0, g1);
    P[1] = pk(g2, g0);
    P[2] = pk(g1, g2);

    const u64* cst2 = (const u64*)cst;               // 36 packed coord pairs
    float4* dst = (float4*)(out + DV_OFF + (size_t)gp * (MA * 3));

#pragma unroll
    for (int r = 0; r < 18; r++) {
        const int p0 = 2 * r, p1 = 2 * r + 1;
        u64 v0 = fma2(cst2[p0], NEG1, P[p0 % 3]);    // g[c] - cs[m][c]
        u64 v1 = fma2(cst2[p1], NEG1, P[p1 % 3]);
        union { u64 d[2]; float4 f; } u;
        u.d[0] = v0; u.d[1] = v1;
        dst[r] = u.f;
    }
}

extern "C" void kernel_launch(void* const* d_in, const int* in_sizes, int n_in,
                              void* d_out, int out_size)
{
    // d_in[0]: labels (int32, unused -- padding is full for every molecule)
    const float* coords = (const float*)d_in[1];
    const float* sphere = (const float*)d_in[2];
    const float* sw     = (const float*)d_in[3];
    float* out = (float*)d_out;

    dim3 gb((MA * MSH + 255) / 256, N_MOL);          // 19 x 8
    becke_kernel<<<gb, 256>>>(coords, sphere, sw, out);

    dim3 gd(2, MA, N_MOL);                            // 2 x 24 x 8
    dv_kernel<<<gd, 256>>>(coords, out);
}

// round 3
// speedup vs baseline: 1.6933x; 1.1472x over previous
#include <cuda_runtime.h>
#include <cuda_bf16.h>

// Problem constants (match reference)
#define N_MOL   8
#define MA      24
#define DESIGN  26
#define RADIAL  15
#define MS      (RADIAL * DESIGN)        // 390 samples per atom
#define MSH     (MS / 2)                 // 195: two points per thread
#define MXP     (MA * MS)                // 9360 grid points per molecule
#define RM_C    5.0f
#define PI_F    3.14159265358979323846f

// Output layout: concat(grid [N,MXP,3], dv [N,MXP,MA,3], weights [N,MXP])
#define GRID_FLOATS (N_MOL * MXP * 3)              // 224640
#define DV_OFF      GRID_FLOATS
#define DV_FLOATS   (N_MOL * MXP * MA * 3)         // 5391360
#define W_OFF       (DV_OFF + DV_FLOATS)           // 5616000
#define DV_VEC4     (DV_FLOATS / 4)                // 1347840 float4 elements

typedef unsigned long long u64;

// ---- packed f32x2 helpers (Blackwell sm_100+; ptxas never auto-fuses) ----
__device__ __forceinline__ u64 pk(float lo, float hi) {
    u64 r; asm("mov.b64 %0, {%1, %2};" : "=l"(r) : "f"(lo), "f"(hi)); return r;
}
__device__ __forceinline__ void upk(u64 v, float& lo, float& hi) {
    asm("mov.b64 {%0, %1}, %2;" : "=f"(lo), "=f"(hi) : "l"(v));
}
__device__ __forceinline__ u64 fma2(u64 a, u64 b, u64 c) {
    u64 r; asm("fma.rn.f32x2 %0, %1, %2, %3;" : "=l"(r) : "l"(a), "l"(b), "l"(c)); return r;
}
__device__ __forceinline__ u64 mul2(u64 a, u64 b) {
    u64 r; asm("mul.rn.f32x2 %0, %1, %2;" : "=l"(r) : "l"(a), "l"(b)); return r;
}
__device__ __forceinline__ u64 add2(u64 a, u64 b) {
    u64 r; asm("add.rn.f32x2 %0, %1, %2;" : "=l"(r) : "l"(a), "l"(b)); return r;
}

// ============================================================================
// Becke kernel: one thread handles TWO grid points (k and k+195) of the same
// owning atom; all pair math packed f32x2.
//   - grid: (37, 8) x 128 threads = 296 blocks -> exactly 2 blocks/SM, no tail
//   - 12 packed ops per pair: softening as mu*(1.5 - 0.5 mu^2); the 0.5 cell
//     prefactors are dropped (uniform 0.5^23 scale cancels in cell_am / sum).
// ============================================================================
__global__ __launch_bounds__(128)
void becke_kernel(const float* __restrict__ coords,   // [N, MA, 3]
                  const float* __restrict__ sphere,   // [DESIGN, 3]
                  const float* __restrict__ sw,       // [DESIGN]
                  float* __restrict__ out)
{
    __shared__ float cs[MA][3];
    __shared__ u64   scs2[MA][3];       // duplicated-packed coords
    __shared__ u64   srdm2[MA][MA];     // duplicated-packed 1/max(dm,1e-12)
    __shared__ float sph[DESIGN][3];
    __shared__ float sws[DESIGN];

    const int nmol = blockIdx.y;
    const int tid  = threadIdx.x;

    if (tid < MA * 3) cs[tid / 3][tid % 3] = coords[nmol * MA * 3 + tid];
    if (tid < DESIGN * 3) sph[tid / 3][tid % 3] = sphere[tid];
    if (tid < DESIGN) sws[tid] = sw[tid];
    __syncthreads();

    for (int e = tid; e < MA * MA; e += 128) {
        int i = e / MA, j = e % MA;
        float dx = cs[i][0] - cs[j][0];
        float dy = cs[i][1] - cs[j][1];
        float dz = cs[i][2] - cs[j][2];
        float d  = sqrtf(dx * dx + dy * dy + dz * dz);
        float rc = 1.0f / fmaxf(d, 1e-12f);
        srdm2[i][j] = pk(rc, rc);
    }
    if (tid < MA * 3) {
        float v = cs[tid / 3][tid % 3];
        scs2[tid / 3][tid % 3] = pk(v, v);
    }
    __syncthreads();

    const int q = blockIdx.x * 128 + tid;        // [0, MA*MSH) per molecule
    if (q >= MA * MSH) return;

    const int am = q / MSH;
    const int k0 = q % MSH;
    const int k1 = k0 + MSH;

    const float cax = cs[am][0], cay = cs[am][1], caz = cs[am][2];

    float gx0, gy0, gz0, wt0, gx1, gy1, gz1, wt1;
    {
        int a = k0 / DESIGN, d = k0 % DESIGN;
        float fi = (float)(a + 1);
        float z  = -cosf(PI_F * (2.0f * fi - 1.0f) / (2.0f * (float)RADIAL));
        float omz = 1.0f - z;
        float r   = RM_C * (1.0f + z) / omz;
        float dr  = 2.0f * RM_C / (omz * omz);
        float w   = sqrtf(1.0f - z * z) * dr * (PI_F / (float)RADIAL);
        wt0 = sws[d] * (r * r * 4.0f * PI_F * w);
        gx0 = cax + r * sph[d][0];
        gy0 = cay + r * sph[d][1];
        gz0 = caz + r * sph[d][2];
    }
    {
        int a = k1 / DESIGN, d = k1 % DESIGN;
        float fi = (float)(a + 1);
        float z  = -cosf(PI_F * (2.0f * fi - 1.0f) / (2.0f * (float)RADIAL));
        float omz = 1.0f - z;
        float r   = RM_C * (1.0f + z) / omz;
        float dr  = 2.0f * RM_C / (omz * omz);
        float w   = sqrtf(1.0f - z * z) * dr * (PI_F / (float)RADIAL);
        wt1 = sws[d] * (r * r * 4.0f * PI_F * w);
        gx1 = cax + r * sph[d][0];
        gy1 = cay + r * sph[d][1];
        gz1 = caz + r * sph[d][2];
    }

    const u64 NEG1 = pk(-1.0f, -1.0f);
    const u64 ONE  = pk(1.0f, 1.0f);
    const u64 C15  = pk(1.5f, 1.5f);
    const u64 CN05 = pk(-0.5f, -0.5f);

    const u64 gx2 = pk(gx0, gx1), gy2 = pk(gy0, gy1), gz2 = pk(gz0, gz1);

    // distances to every atom, packed
    u64 rx2[MA];
#pragma unroll
    for (int j = 0; j < MA; j++) {
        u64 dx = fma2(scs2[j][0], NEG1, gx2);
        u64 dy = fma2(scs2[j][1], NEG1, gy2);
        u64 dz = fma2(scs2[j][2], NEG1, gz2);
        u64 s  = mul2(dx, dx);
        s = fma2(dy, dy, s);
        s = fma2(dz, dz, s);
        float s0, s1; upk(s, s0, s1);
        rx2[j] = pk(sqrtf(s0), sqrtf(s1));
    }

    // Becke cell functions, each unordered pair once (mu_ji = -mu_ij).
    // 0.5 prefactors dropped: uniform 0.5^23 scale cancels in the ratio.
    u64 cell2[MA];
#pragma unroll
    for (int j = 0; j < MA; j++) cell2[j] = ONE;

#pragma unroll
    for (int i = 0; i < MA; i++) {
#pragma unroll
        for (int j = i + 1; j < MA; j++) {
            u64 dif = fma2(rx2[j], NEG1, rx2[i]);
            u64 mu  = mul2(dif, srdm2[i][j]);
            // softening: mu = mu * (1.5 - 0.5*mu^2), twice
            u64 m2 = mul2(mu, mu);
            mu = mul2(mu, fma2(m2, CN05, C15));
            m2 = mul2(mu, mu);
            mu = mul2(mu, fma2(m2, CN05, C15));
            // cell[i] *= (1 - mu); cell[j] *= (1 + mu)
            cell2[i] = mul2(cell2[i], fma2(mu, NEG1, ONE));
            cell2[j] = mul2(cell2[j], add2(mu, ONE));
        }
    }

    u64 ssum = cell2[0];
#pragma unroll
    for (int j = 1; j < MA; j++) ssum = add2(ssum, cell2[j]);

    u64 cam2 = cell2[0];
#pragma unroll
    for (int j = 1; j < MA; j++) if (j == am) cam2 = cell2[j];

    float s0, s1, c0, c1;
    upk(ssum, s0, s1);
    upk(cam2, c0, c1);
    const float v0 = c0 / s0;
    const float v1 = c1 / s1;

    const int gp0 = nmol * MXP + am * MS + k0;
    const int gp1 = gp0 + MSH;
    out[3 * gp0 + 0] = gx0;
    out[3 * gp0 + 1] = gy0;
    out[3 * gp0 + 2] = gz0;
    out[3 * gp1 + 0] = gx1;
    out[3 * gp1 + 1] = gy1;
    out[3 * gp1 + 2] = gz1;
    out[W_OFF + gp0] = v0 * wt0;
    out[W_OFF + gp1] = v1 * wt1;
}

// ============================================================================
// dv kernel: one thread per LINEAR float4 of the dv region -> consecutive
// threads store consecutive 16B chunks (perfect coalescing).
// Each dv row is exactly 18 float4 (72 floats), so a float4 never straddles
// rows:  f -> gp = f/18, r = f%18.
//   dv[e] = g[gp][(4r+i)%3] - coords_flat[n][4r+i],  (4r+i)%3 == (r+i)%3
// Grid section of `out` (written by becke) is L2-hot; coords float4 loads
// are aligned (row stride 288B, offset 16r).
// ============================================================================
__global__ __launch_bounds__(256)
void dv_kernel(const float* __restrict__ coords, float* __restrict__ out)
{
    const int f = blockIdx.x * 256 + threadIdx.x;   // exact: 5265*256 = DV_VEC4

    const int gp = f / 18;
    const int r  = f - gp * 18;
    const int n  = gp / MXP;

    const float g0 = out[3 * gp + 0];
    const float g1 = out[3 * gp + 1];
    const float g2 = out[3 * gp + 2];

    const int rm = r % 3;   // c for element 4r
    // cyclic pattern (g[rm], g[rm+1], g[rm+2], g[rm]) (indices mod 3)
    const float pa = (rm == 0) ? g0 : ((rm == 1) ? g1 : g2);
    const float pb = (rm == 0) ? g1 : ((rm == 1) ? g2 : g0);
    const float pc = (rm == 0) ? g2 : ((rm == 1) ? g0 : g1);

    const float4 c4 = __ldg((const float4*)(coords + n * (MA * 3)) + r);

    float4 o;
    o.x = pa - c4.x;
    o.y = pb - c4.y;
    o.z = pc - c4.z;
    o.w = pa - c4.w;

    ((float4*)(out + DV_OFF))[f] = o;
}

extern "C" void kernel_launch(void* const* d_in, const int* in_sizes, int n_in,
                              void* d_out, int out_size)
{
    // d_in[0]: labels (int32, unused -- padding is full for every molecule)
    const float* coords = (const float*)d_in[1];
    const float* sphere = (const float*)d_in[2];
    const float* sw     = (const float*)d_in[3];
    float* out = (float*)d_out;

    dim3 gb(37, N_MOL);                       // 296 blocks of 128 = 2/SM exact
    becke_kernel<<<gb, 128>>>(coords, sphere, sw, out);

    dv_kernel<<<DV_VEC4 / 256, 256>>>(coords, out);
}